// round 7
// baseline (speedup 1.0000x reference)
#include <cuda_runtime.h>

#define BS   4
#define SEQ  2048
#define DIM  1024
#define NH   16
#define DPH  64
#define MROWS (BS * SEQ)

// Scratch (allocation-free rule: __device__ globals)
__device__ float g_q[(size_t)MROWS * DIM];
__device__ float g_k[(size_t)MROWS * DIM];
__device__ float g_v[(size_t)MROWS * DIM];
__device__ float g_ctx[(size_t)MROWS * DIM];

// ---------------------------------------------------------------------------
// C = (A @ B^T + bias) * scale
// A: [M=8192][K=1024] row-major (K contiguous)
// B: [N=1024][K=1024] row-major (K contiguous)  (torch Linear weight)
// SPLIT=1: scatter output into (b, h, s, d) head-split layout
// SPLIT=0: plain row-major [M][N]
// Block: 64x64 tile, 256 threads, 4x4 microtile, BK=16.
// ---------------------------------------------------------------------------
template <int SPLIT>
__global__ __launch_bounds__(256) void gemm_bias_nt(
    const float* __restrict__ A, const float* __restrict__ B,
    const float* __restrict__ bias, float* __restrict__ C, float scale)
{
    const int K = DIM;
    __shared__ float As[16][68];   // k-major, padded
    __shared__ float Bs[16][68];

    int t  = threadIdx.x;
    int tx = t & 15, ty = t >> 4;
    int m0 = blockIdx.y * 64, n0 = blockIdx.x * 64;

    int lrow = t >> 2;             // 0..63
    int lk   = (t & 3) << 2;       // 0,4,8,12
    const float* Ap = A + (size_t)(m0 + lrow) * K + lk;
    const float* Bp = B + (size_t)(n0 + lrow) * K + lk;

    float acc[4][4];
    #pragma unroll
    for (int i = 0; i < 4; i++)
        #pragma unroll
        for (int j = 0; j < 4; j++) acc[i][j] = 0.f;

    for (int k0 = 0; k0 < K; k0 += 16) {
        float4 av = *(const float4*)(Ap + k0);
        float4 bv = *(const float4*)(Bp + k0);
        __syncthreads();  // protect previous iteration's reads
        As[lk + 0][lrow] = av.x; As[lk + 1][lrow] = av.y;
        As[lk + 2][lrow] = av.z; As[lk + 3][lrow] = av.w;
        Bs[lk + 0][lrow] = bv.x; Bs[lk + 1][lrow] = bv.y;
        Bs[lk + 2][lrow] = bv.z; Bs[lk + 3][lrow] = bv.w;
        __syncthreads();

        #pragma unroll
        for (int kk = 0; kk < 16; kk++) {
            float4 a = *(const float4*)&As[kk][ty << 2];
            float4 b = *(const float4*)&Bs[kk][tx << 2];
            float ar[4] = {a.x, a.y, a.z, a.w};
            float br[4] = {b.x, b.y, b.z, b.w};
            #pragma unroll
            for (int i = 0; i < 4; i++)
                #pragma unroll
                for (int j = 0; j < 4; j++)
                    acc[i][j] = fmaf(ar[i], br[j], acc[i][j]);
        }
    }

    #pragma unroll
    for (int i = 0; i < 4; i++) {
        int m = m0 + (ty << 2) + i;
        #pragma unroll
        for (int j = 0; j < 4; j++) {
            int n = n0 + (tx << 2) + j;
            float v = (acc[i][j] + bias[n]) * scale;
            if (SPLIT) {
                int b = m >> 11;          // / SEQ
                int s = m & (SEQ - 1);
                int h = n >> 6;           // / DPH
                int d = n & 63;
                C[(((size_t)(b * NH + h) * SEQ + s) << 6) + d] = v;
            } else {
                C[(size_t)m * DIM + n] = v;
            }
        }
    }
}

// ---------------------------------------------------------------------------
// Flash attention, fp32. One block = one (b, h) and 64 query rows.
// 256 threads (16x16), 4x4 microtiles for both S=QK^T and O+=P*V.
// Online softmax; per-row stats replicated across the 16 tx-lanes via shfl.
// Mask is read as int32 (harness serializes jax bool as int32).
// ---------------------------------------------------------------------------
__global__ __launch_bounds__(256) void attn_kernel(
    const float* __restrict__ q, const float* __restrict__ k,
    const float* __restrict__ v, const int* __restrict__ mask,
    float* __restrict__ ctx)
{
    extern __shared__ float sm[];
    float* Qt = sm;                 // [64 d][68] transposed (d-major)
    float* Kt = sm + 64 * 68;       // [64 d][68] transposed
    float* Vs = sm + 2 * 64 * 68;   // [64 key][68] row-major
    float* Ps = sm + 3 * 64 * 68;   // [64 key][68] key-major (P^T)
    __shared__ int msk[64];

    int b = blockIdx.z, h = blockIdx.y, qt = blockIdx.x;
    int t  = threadIdx.x;
    int tx = t & 15, ty = t >> 4;

    size_t head_off = (size_t)(b * NH + h) * SEQ * DPH;
    const float* qb = q + head_off + (size_t)qt * 64 * DPH;
    const float* kb = k + head_off;
    const float* vb = v + head_off;

    // Load Q tile transposed: Qt[d][row]
    #pragma unroll
    for (int i = 0; i < 4; i++) {
        int f = t + i * 256;
        int row = f >> 4, dg = (f & 15) << 2;
        float4 qv = *(const float4*)(qb + row * DPH + dg);
        Qt[(dg + 0) * 68 + row] = qv.x;
        Qt[(dg + 1) * 68 + row] = qv.y;
        Qt[(dg + 2) * 68 + row] = qv.z;
        Qt[(dg + 3) * 68 + row] = qv.w;
    }

    float m_[4], l_[4], o[4][4];
    #pragma unroll
    for (int i = 0; i < 4; i++) {
        m_[i] = -1e30f; l_[i] = 0.f;
        #pragma unroll
        for (int j = 0; j < 4; j++) o[i][j] = 0.f;
    }

    for (int kt = 0; kt < SEQ / 64; kt++) {
        __syncthreads();  // previous iteration done with Kt/Vs/Ps
        #pragma unroll
        for (int i = 0; i < 4; i++) {
            int f = t + i * 256;
            int row = f >> 4, dg = (f & 15) << 2;
            const float* kp = kb + (size_t)(kt * 64 + row) * DPH + dg;
            float4 kv = *(const float4*)kp;
            Kt[(dg + 0) * 68 + row] = kv.x;
            Kt[(dg + 1) * 68 + row] = kv.y;
            Kt[(dg + 2) * 68 + row] = kv.z;
            Kt[(dg + 3) * 68 + row] = kv.w;
            const float* vp = vb + (size_t)(kt * 64 + row) * DPH + dg;
            *(float4*)&Vs[row * 68 + dg] = *(const float4*)vp;
        }
        if (t < 64) msk[t] = mask[b * SEQ + kt * 64 + t];
        __syncthreads();

        // S = Q K^T (K-dim = DPH = 64, fully resident)
        float s[4][4];
        #pragma unroll
        for (int i = 0; i < 4; i++)
            #pragma unroll
            for (int j = 0; j < 4; j++) s[i][j] = 0.f;

        #pragma unroll
        for (int d = 0; d < 64; d++) {
            float4 a  = *(const float4*)&Qt[d * 68 + (ty << 2)];
            float4 bb = *(const float4*)&Kt[d * 68 + (tx << 2)];
            float ar[4] = {a.x, a.y, a.z, a.w};
            float br[4] = {bb.x, bb.y, bb.z, bb.w};
            #pragma unroll
            for (int i = 0; i < 4; i++)
                #pragma unroll
                for (int j = 0; j < 4; j++)
                    s[i][j] = fmaf(ar[i], br[j], s[i][j]);
        }

        // key padding mask (column = key); nonzero = valid
        #pragma unroll
        for (int j = 0; j < 4; j++) {
            if (msk[(tx << 2) + j] == 0) {
                #pragma unroll
                for (int i = 0; i < 4; i++) s[i][j] = -1e30f;
            }
        }

        // Online softmax per owned row. Lanes with same ty occupy a 16-lane
        // half-warp, so xor-shuffles with offsets 8..1 reduce across tx.
        #pragma unroll
        for (int i = 0; i < 4; i++) {
            float rm = fmaxf(fmaxf(s[i][0], s[i][1]), fmaxf(s[i][2], s[i][3]));
            #pragma unroll
            for (int off = 8; off; off >>= 1)
                rm = fmaxf(rm, __shfl_xor_sync(0xffffffffu, rm, off));
            float mnew = fmaxf(m_[i], rm);
            float corr = __expf(m_[i] - mnew);
            float rs = 0.f;
            #pragma unroll
            for (int j = 0; j < 4; j++) {
                float p = __expf(s[i][j] - mnew);
                s[i][j] = p;
                rs += p;
            }
            #pragma unroll
            for (int off = 8; off; off >>= 1)
                rs += __shfl_xor_sync(0xffffffffu, rs, off);
            l_[i] = l_[i] * corr + rs;
            m_[i] = mnew;
            #pragma unroll
            for (int j = 0; j < 4; j++) o[i][j] *= corr;
        }

        // Stage P transposed for the PV GEMM
        #pragma unroll
        for (int i = 0; i < 4; i++)
            #pragma unroll
            for (int j = 0; j < 4; j++)
                Ps[((tx << 2) + j) * 68 + (ty << 2) + i] = s[i][j];
        __syncthreads();

        // O += P * V
        #pragma unroll
        for (int jj = 0; jj < 64; jj++) {
            float4 p  = *(const float4*)&Ps[jj * 68 + (ty << 2)];
            float4 vv = *(const float4*)&Vs[jj * 68 + (tx << 2)];
            float pr[4] = {p.x, p.y, p.z, p.w};
            float vr[4] = {vv.x, vv.y, vv.z, vv.w};
            #pragma unroll
            for (int i = 0; i < 4; i++)
                #pragma unroll
                for (int j = 0; j < 4; j++)
                    o[i][j] = fmaf(pr[i], vr[j], o[i][j]);
        }
    }

    // Write context in (b, s, dim) layout for the output projection
    #pragma unroll
    for (int i = 0; i < 4; i++) {
        int srow = qt * 64 + (ty << 2) + i;
        float inv = 1.0f / l_[i];
        float4 out;
        out.x = o[i][0] * inv;
        out.y = o[i][1] * inv;
        out.z = o[i][2] * inv;
        out.w = o[i][3] * inv;
        size_t base = ((size_t)b * SEQ + srow) * DIM + h * DPH + (tx << 2);
        *(float4*)&ctx[base] = out;
    }
}

// ---------------------------------------------------------------------------
extern "C" void kernel_launch(void* const* d_in, const int* in_sizes, int n_in,
                              void* d_out, int out_size)
{
    const float* query = (const float*)d_in[0];
    const float* key_  = (const float*)d_in[1];
    const float* value = (const float*)d_in[2];
    const int*   mask  = (const int*)d_in[3];   // jax bool -> int32 in harness
    const float* Wq = (const float*)d_in[4];
    const float* bq = (const float*)d_in[5];
    const float* Wk = (const float*)d_in[6];
    const float* bk = (const float*)d_in[7];
    const float* Wv = (const float*)d_in[8];
    const float* bv = (const float*)d_in[9];
    const float* Wo = (const float*)d_in[10];
    const float* bo = (const float*)d_in[11];
    float* out = (float*)d_out;

    float *pq, *pk, *pv, *pctx;
    cudaGetSymbolAddress((void**)&pq,   g_q);
    cudaGetSymbolAddress((void**)&pk,   g_k);
    cudaGetSymbolAddress((void**)&pv,   g_v);
    cudaGetSymbolAddress((void**)&pctx, g_ctx);

    const int attn_smem = 4 * 64 * 68 * (int)sizeof(float);  // 69632 B
    cudaFuncSetAttribute(attn_kernel,
                         cudaFuncAttributeMaxDynamicSharedMemorySize, attn_smem);

    dim3 gblk(DIM / 64, MROWS / 64);  // (16, 128)

    // Projections: q scaled by 1/sqrt(DPH) = 1/8 (applied after bias, per ref)
    gemm_bias_nt<1><<<gblk, 256>>>(query, Wq, bq, pq, 0.125f);
    gemm_bias_nt<1><<<gblk, 256>>>(key_,  Wk, bk, pk, 1.0f);
    gemm_bias_nt<1><<<gblk, 256>>>(value, Wv, bv, pv, 1.0f);

    // Attention: grid (q-tiles, heads, batch)
    attn_kernel<<<dim3(SEQ / 64, NH, BS), 256, attn_smem>>>(pq, pk, pv, mask, pctx);

    // Output projection straight into d_out
    gemm_bias_nt<0><<<gblk, 256>>>(pctx, Wo, bo, out, 1.0f);
}

// round 8
// speedup vs baseline: 1.3721x; 1.3721x over previous
#include <cuda_runtime.h>
#include <cuda_bf16.h>
#include <cstdint>

#define BS   4
#define SEQ  2048
#define DIM  1024
#define NH   16
#define DPH  64
#define MROWS (BS * SEQ)

// Scratch (allocation-free rule: __device__ globals)
__device__ float g_q[(size_t)MROWS * DIM];
__device__ float g_k[(size_t)MROWS * DIM];
__device__ float g_v[(size_t)MROWS * DIM];
__device__ float g_ctx[(size_t)MROWS * DIM];

// ---------------------------------------------------------------------------
// bf16x3 helpers
// ---------------------------------------------------------------------------
__device__ __forceinline__ uint32_t pk_bf16(float a, float b) {
    unsigned short ha = __bfloat16_as_ushort(__float2bfloat16_rn(a));
    unsigned short hb = __bfloat16_as_ushort(__float2bfloat16_rn(b));
    return (uint32_t)ha | ((uint32_t)hb << 16);
}

__device__ __forceinline__ void mma_bf16(float* c, uint32_t a0, uint32_t a1,
                                         uint32_t a2, uint32_t a3,
                                         uint32_t b0, uint32_t b1) {
    asm volatile(
        "mma.sync.aligned.m16n8k16.row.col.f32.bf16.bf16.f32 "
        "{%0,%1,%2,%3}, {%4,%5,%6,%7}, {%8,%9}, {%0,%1,%2,%3};"
        : "+f"(c[0]), "+f"(c[1]), "+f"(c[2]), "+f"(c[3])
        : "r"(a0), "r"(a1), "r"(a2), "r"(a3), "r"(b0), "r"(b1));
}

// ---------------------------------------------------------------------------
// Tensor-core GEMM (bf16x3): C = (A @ B^T + bias) * scale
// A: [M][K=1024] row-major, B: [N][K=1024] row-major (torch Linear weight).
// Block tile 128x128, BK=32, 256 threads = 8 warps (4 warp-rows x 2 warp-cols),
// warp tile 32x64 = 2 m-frags x 8 n-frags of m16n8k16.
// Each element split x = hi + lo (bf16); product uses Ah*Bh + Ah*Bl + Al*Bh.
// SPLIT=1: scatter into (b,h,s,d) head-split layout; SPLIT=0: row-major [M][N].
// ---------------------------------------------------------------------------
#define SROW 20   // smem row stride in 32-bit words (40 bf16) -> conflict-free

template <int SPLIT>
__global__ __launch_bounds__(256) void gemm_tc(
    const float* __restrict__ A, const float* __restrict__ B,
    const float* __restrict__ bias, float* __restrict__ C, float scale)
{
    const int K = DIM;
    __shared__ uint32_t Ah[128 * SROW], Al[128 * SROW];
    __shared__ uint32_t Bh[128 * SROW], Bl[128 * SROW];

    const int t    = threadIdx.x;
    const int warp = t >> 5;
    const int lane = t & 31;
    const int g    = lane >> 2;      // 0..7
    const int tig  = lane & 3;       // 0..3
    const int wrow = warp & 3;       // 4 warp rows  (32 rows each)
    const int wcol = warp >> 2;      // 2 warp cols  (64 cols each)

    const int m0 = blockIdx.y * 128;
    const int n0 = blockIdx.x * 128;

    float acc[2][8][4];
    #pragma unroll
    for (int i = 0; i < 2; i++)
        #pragma unroll
        for (int j = 0; j < 8; j++)
            #pragma unroll
            for (int c = 0; c < 4; c++) acc[i][j][c] = 0.f;

    // global load indices: 128 rows x 8 float4 per tile = 1024 f4, 4 per thread
    const int lrow[4] = { (t + 0) >> 3, (t + 256) >> 3, (t + 512) >> 3, (t + 768) >> 3 };
    const int lkq    = (t & 7) << 2;   // 0,4,...,28 (same for all 4 iters)

    float4 areg[4], breg[4];
    #pragma unroll
    for (int i = 0; i < 4; i++) {
        areg[i] = *(const float4*)(A + (size_t)(m0 + lrow[i]) * K + lkq);
        breg[i] = *(const float4*)(B + (size_t)(n0 + lrow[i]) * K + lkq);
    }

    for (int k0 = 0; k0 < K; k0 += 32) {
        __syncthreads();   // previous compute done with smem
        #pragma unroll
        for (int i = 0; i < 4; i++) {
            float ax = areg[i].x, ay = areg[i].y, az = areg[i].z, aw = areg[i].w;
            float hx = __bfloat162float(__float2bfloat16_rn(ax));
            float hy = __bfloat162float(__float2bfloat16_rn(ay));
            float hz = __bfloat162float(__float2bfloat16_rn(az));
            float hw = __bfloat162float(__float2bfloat16_rn(aw));
            int base = lrow[i] * SROW + (lkq >> 1);
            Ah[base + 0] = pk_bf16(hx, hy);
            Ah[base + 1] = pk_bf16(hz, hw);
            Al[base + 0] = pk_bf16(ax - hx, ay - hy);
            Al[base + 1] = pk_bf16(az - hz, aw - hw);

            float bx = breg[i].x, by = breg[i].y, bz = breg[i].z, bw = breg[i].w;
            float gx = __bfloat162float(__float2bfloat16_rn(bx));
            float gy = __bfloat162float(__float2bfloat16_rn(by));
            float gz = __bfloat162float(__float2bfloat16_rn(bz));
            float gw = __bfloat162float(__float2bfloat16_rn(bw));
            Bh[base + 0] = pk_bf16(gx, gy);
            Bh[base + 1] = pk_bf16(gz, gw);
            Bl[base + 0] = pk_bf16(bx - gx, by - gy);
            Bl[base + 1] = pk_bf16(bz - gz, bw - gw);
        }
        __syncthreads();

        if (k0 + 32 < K) {
            #pragma unroll
            for (int i = 0; i < 4; i++) {
                areg[i] = *(const float4*)(A + (size_t)(m0 + lrow[i]) * K + k0 + 32 + lkq);
                breg[i] = *(const float4*)(B + (size_t)(n0 + lrow[i]) * K + k0 + 32 + lkq);
            }
        }

        #pragma unroll
        for (int ks = 0; ks < 2; ks++) {
            const int kw = ks * 8 + tig;   // word offset within row
            uint32_t ah[2][4], al[2][4];
            #pragma unroll
            for (int mt = 0; mt < 2; mt++) {
                int rm = wrow * 32 + mt * 16;
                ah[mt][0] = Ah[(rm + g)     * SROW + kw];
                ah[mt][1] = Ah[(rm + g + 8) * SROW + kw];
                ah[mt][2] = Ah[(rm + g)     * SROW + kw + 4];
                ah[mt][3] = Ah[(rm + g + 8) * SROW + kw + 4];
                al[mt][0] = Al[(rm + g)     * SROW + kw];
                al[mt][1] = Al[(rm + g + 8) * SROW + kw];
                al[mt][2] = Al[(rm + g)     * SROW + kw + 4];
                al[mt][3] = Al[(rm + g + 8) * SROW + kw + 4];
            }
            #pragma unroll
            for (int nt = 0; nt < 8; nt++) {
                int cn = wcol * 64 + nt * 8;
                uint32_t bh0 = Bh[(cn + g) * SROW + kw];
                uint32_t bh1 = Bh[(cn + g) * SROW + kw + 4];
                uint32_t bl0 = Bl[(cn + g) * SROW + kw];
                uint32_t bl1 = Bl[(cn + g) * SROW + kw + 4];
                #pragma unroll
                for (int mt = 0; mt < 2; mt++) {
                    mma_bf16(acc[mt][nt], ah[mt][0], ah[mt][1], ah[mt][2], ah[mt][3], bh0, bh1);
                    mma_bf16(acc[mt][nt], ah[mt][0], ah[mt][1], ah[mt][2], ah[mt][3], bl0, bl1);
                    mma_bf16(acc[mt][nt], al[mt][0], al[mt][1], al[mt][2], al[mt][3], bh0, bh1);
                }
            }
        }
    }

    // Epilogue: c0=C[g][2tig], c1=C[g][2tig+1], c2=C[g+8][2tig], c3=C[g+8][2tig+1]
    #pragma unroll
    for (int mt = 0; mt < 2; mt++) {
        #pragma unroll
        for (int nt = 0; nt < 8; nt++) {
            int n = n0 + wcol * 64 + nt * 8 + (tig << 1);
            float b0 = bias[n], b1 = bias[n + 1];
            #pragma unroll
            for (int half = 0; half < 2; half++) {
                int m = m0 + wrow * 32 + mt * 16 + g + half * 8;
                float v0 = (acc[mt][nt][half * 2 + 0] + b0) * scale;
                float v1 = (acc[mt][nt][half * 2 + 1] + b1) * scale;
                if (SPLIT) {
                    int bb = m >> 11;          // / SEQ
                    int s  = m & (SEQ - 1);
                    int h  = n >> 6;           // / DPH
                    int d  = n & 63;
                    size_t base = (((size_t)(bb * NH + h) * SEQ + s) << 6) + d;
                    C[base]     = v0;
                    C[base + 1] = v1;
                } else {
                    float2 o = make_float2(v0, v1);
                    *(float2*)&C[(size_t)m * DIM + n] = o;
                }
            }
        }
    }
}

// ---------------------------------------------------------------------------
// Flash attention, fp32 (unchanged from round 7 passing version).
// ---------------------------------------------------------------------------
__global__ __launch_bounds__(256) void attn_kernel(
    const float* __restrict__ q, const float* __restrict__ k,
    const float* __restrict__ v, const int* __restrict__ mask,
    float* __restrict__ ctx)
{
    extern __shared__ float sm[];
    float* Qt = sm;                 // [64 d][68] transposed (d-major)
    float* Kt = sm + 64 * 68;       // [64 d][68] transposed
    float* Vs = sm + 2 * 64 * 68;   // [64 key][68] row-major
    float* Ps = sm + 3 * 64 * 68;   // [64 key][68] key-major (P^T)
    __shared__ int msk[64];

    int b = blockIdx.z, h = blockIdx.y, qt = blockIdx.x;
    int t  = threadIdx.x;
    int tx = t & 15, ty = t >> 4;

    size_t head_off = (size_t)(b * NH + h) * SEQ * DPH;
    const float* qb = q + head_off + (size_t)qt * 64 * DPH;
    const float* kb = k + head_off;
    const float* vb = v + head_off;

    #pragma unroll
    for (int i = 0; i < 4; i++) {
        int f = t + i * 256;
        int row = f >> 4, dg = (f & 15) << 2;
        float4 qv = *(const float4*)(qb + row * DPH + dg);
        Qt[(dg + 0) * 68 + row] = qv.x;
        Qt[(dg + 1) * 68 + row] = qv.y;
        Qt[(dg + 2) * 68 + row] = qv.z;
        Qt[(dg + 3) * 68 + row] = qv.w;
    }

    float m_[4], l_[4], o[4][4];
    #pragma unroll
    for (int i = 0; i < 4; i++) {
        m_[i] = -1e30f; l_[i] = 0.f;
        #pragma unroll
        for (int j = 0; j < 4; j++) o[i][j] = 0.f;
    }

    for (int kt = 0; kt < SEQ / 64; kt++) {
        __syncthreads();
        #pragma unroll
        for (int i = 0; i < 4; i++) {
            int f = t + i * 256;
            int row = f >> 4, dg = (f & 15) << 2;
            const float* kp = kb + (size_t)(kt * 64 + row) * DPH + dg;
            float4 kv = *(const float4*)kp;
            Kt[(dg + 0) * 68 + row] = kv.x;
            Kt[(dg + 1) * 68 + row] = kv.y;
            Kt[(dg + 2) * 68 + row] = kv.z;
            Kt[(dg + 3) * 68 + row] = kv.w;
            const float* vp = vb + (size_t)(kt * 64 + row) * DPH + dg;
            *(float4*)&Vs[row * 68 + dg] = *(const float4*)vp;
        }
        if (t < 64) msk[t] = mask[b * SEQ + kt * 64 + t];
        __syncthreads();

        float s[4][4];
        #pragma unroll
        for (int i = 0; i < 4; i++)
            #pragma unroll
            for (int j = 0; j < 4; j++) s[i][j] = 0.f;

        #pragma unroll
        for (int d = 0; d < 64; d++) {
            float4 a  = *(const float4*)&Qt[d * 68 + (ty << 2)];
            float4 bb = *(const float4*)&Kt[d * 68 + (tx << 2)];
            float ar[4] = {a.x, a.y, a.z, a.w};
            float br[4] = {bb.x, bb.y, bb.z, bb.w};
            #pragma unroll
            for (int i = 0; i < 4; i++)
                #pragma unroll
                for (int j = 0; j < 4; j++)
                    s[i][j] = fmaf(ar[i], br[j], s[i][j]);
        }

        #pragma unroll
        for (int j = 0; j < 4; j++) {
            if (msk[(tx << 2) + j] == 0) {
                #pragma unroll
                for (int i = 0; i < 4; i++) s[i][j] = -1e30f;
            }
        }

        #pragma unroll
        for (int i = 0; i < 4; i++) {
            float rm = fmaxf(fmaxf(s[i][0], s[i][1]), fmaxf(s[i][2], s[i][3]));
            #pragma unroll
            for (int off = 8; off; off >>= 1)
                rm = fmaxf(rm, __shfl_xor_sync(0xffffffffu, rm, off));
            float mnew = fmaxf(m_[i], rm);
            float corr = __expf(m_[i] - mnew);
            float rs = 0.f;
            #pragma unroll
            for (int j = 0; j < 4; j++) {
                float p = __expf(s[i][j] - mnew);
                s[i][j] = p;
                rs += p;
            }
            #pragma unroll
            for (int off = 8; off; off >>= 1)
                rs += __shfl_xor_sync(0xffffffffu, rs, off);
            l_[i] = l_[i] * corr + rs;
            m_[i] = mnew;
            #pragma unroll
            for (int j = 0; j < 4; j++) o[i][j] *= corr;
        }

        #pragma unroll
        for (int i = 0; i < 4; i++)
            #pragma unroll
            for (int j = 0; j < 4; j++)
                Ps[((tx << 2) + j) * 68 + (ty << 2) + i] = s[i][j];
        __syncthreads();

        #pragma unroll
        for (int jj = 0; jj < 64; jj++) {
            float4 p  = *(const float4*)&Ps[jj * 68 + (ty << 2)];
            float4 vv = *(const float4*)&Vs[jj * 68 + (tx << 2)];
            float pr[4] = {p.x, p.y, p.z, p.w};
            float vr[4] = {vv.x, vv.y, vv.z, vv.w};
            #pragma unroll
            for (int i = 0; i < 4; i++)
                #pragma unroll
                for (int j = 0; j < 4; j++)
                    o[i][j] = fmaf(pr[i], vr[j], o[i][j]);
        }
    }

    #pragma unroll
    for (int i = 0; i < 4; i++) {
        int srow = qt * 64 + (ty << 2) + i;
        float inv = 1.0f / l_[i];
        float4 out;
        out.x = o[i][0] * inv;
        out.y = o[i][1] * inv;
        out.z = o[i][2] * inv;
        out.w = o[i][3] * inv;
        size_t base = ((size_t)b * SEQ + srow) * DIM + h * DPH + (tx << 2);
        *(float4*)&ctx[base] = out;
    }
}

// ---------------------------------------------------------------------------
extern "C" void kernel_launch(void* const* d_in, const int* in_sizes, int n_in,
                              void* d_out, int out_size)
{
    const float* query = (const float*)d_in[0];
    const float* key_  = (const float*)d_in[1];
    const float* value = (const float*)d_in[2];
    const int*   mask  = (const int*)d_in[3];   // jax bool -> int32 in harness
    const float* Wq = (const float*)d_in[4];
    const float* bq = (const float*)d_in[5];
    const float* Wk = (const float*)d_in[6];
    const float* bk = (const float*)d_in[7];
    const float* Wv = (const float*)d_in[8];
    const float* bv = (const float*)d_in[9];
    const float* Wo = (const float*)d_in[10];
    const float* bo = (const float*)d_in[11];
    float* out = (float*)d_out;

    float *pq, *pk, *pv, *pctx;
    cudaGetSymbolAddress((void**)&pq,   g_q);
    cudaGetSymbolAddress((void**)&pk,   g_k);
    cudaGetSymbolAddress((void**)&pv,   g_v);
    cudaGetSymbolAddress((void**)&pctx, g_ctx);

    const int attn_smem = 4 * 64 * 68 * (int)sizeof(float);  // 69632 B
    cudaFuncSetAttribute(attn_kernel,
                         cudaFuncAttributeMaxDynamicSharedMemorySize, attn_smem);

    dim3 gg(DIM / 128, MROWS / 128);   // (8, 64)

    // Projections: q scaled by 1/sqrt(DPH) = 1/8 (applied after bias, per ref)
    gemm_tc<1><<<gg, 256>>>(query, Wq, bq, pq, 0.125f);
    gemm_tc<1><<<gg, 256>>>(key_,  Wk, bk, pk, 1.0f);
    gemm_tc<1><<<gg, 256>>>(value, Wv, bv, pv, 1.0f);

    // Attention: grid (q-tiles, heads, batch)
    attn_kernel<<<dim3(SEQ / 64, NH, BS), 256, attn_smem>>>(pq, pk, pv, mask, pctx);

    // Output projection straight into d_out
    gemm_tc<0><<<gg, 256>>>(pctx, Wo, bo, out, 1.0f);
}